// round 15
// baseline (speedup 1.0000x reference)
#include <cuda_runtime.h>
#include <cuda_fp16.h>
#include <cstdint>

#define HID 128
#define NNODES 100000

// Node projections, fp16: P[node][0:128] = x@W1[0:128], [128:256] = x@W1[128:256]
__device__ __half g_Ph[(size_t)NNODES * 256];
// W1 packed into fp16 m16n8k16 B-fragment order: [2 halves][8 kc][16 nf][32 lanes] uint2
__device__ uint2 g_W1fh[2 * 8 * 16 * 32];

// ----------------------------------------------------------------------------
// mma helpers (portable: sm_103 PTX target has no tcgen05)
// ----------------------------------------------------------------------------
__device__ __forceinline__ void mma_f16(float* d, const uint32_t* a, uint32_t b0, uint32_t b1) {
    asm volatile(
        "mma.sync.aligned.m16n8k16.row.col.f32.f16.f16.f32 "
        "{%0,%1,%2,%3}, {%4,%5,%6,%7}, {%8,%9}, {%0,%1,%2,%3};"
        : "+f"(d[0]), "+f"(d[1]), "+f"(d[2]), "+f"(d[3])
        : "r"(a[0]), "r"(a[1]), "r"(a[2]), "r"(a[3]), "r"(b0), "r"(b1));
}

__device__ __forceinline__ void ldmatrix_x4(uint32_t* r, uint32_t smem_addr) {
    asm volatile(
        "ldmatrix.sync.aligned.m8n8.x4.shared.b16 {%0,%1,%2,%3}, [%4];"
        : "=r"(r[0]), "=r"(r[1]), "=r"(r[2]), "=r"(r[3])
        : "r"(smem_addr));
}

__device__ __forceinline__ uint32_t h2_as_u32(__half2 h) {
    uint32_t u;
    memcpy(&u, &h, 4);
    return u;
}
__device__ __forceinline__ __half2 u32_as_h2(uint32_t u) {
    __half2 h;
    memcpy(&h, &u, 4);
    return h;
}

// ----------------------------------------------------------------------------
// Kernel 0: pack W1 into fp16 m16n8k16 B-fragment order (once; 64KB, L2-hot).
// ----------------------------------------------------------------------------
__global__ void pack_w1_kernel(const float* __restrict__ W1)
{
    int i = blockIdx.x * blockDim.x + threadIdx.x;
    if (i >= 2 * 8 * 16 * 32) return;
    int o  = i >> 12;
    int kc = (i >> 9) & 7;
    int nf = (i >> 5) & 15;
    int ln = i & 31;
    int g  = ln >> 2, tq = ln & 3;
    int n  = nf * 8 + g;
    int k0 = o * 128 + kc * 16 + 2 * tq;
    __half2 b0 = __floats2half2_rn(W1[(size_t)k0 * HID + n],       W1[(size_t)(k0 + 1) * HID + n]);
    __half2 b1 = __floats2half2_rn(W1[(size_t)(k0 + 8) * HID + n], W1[(size_t)(k0 + 9) * HID + n]);
    g_W1fh[i] = make_uint2(h2_as_u32(b0), h2_as_u32(b1));
}

// ----------------------------------------------------------------------------
// Kernel 1: node projection via fp16 mma. Full K=128 A-tile resident in smem
// (staged ONCE), then both W halves (o=0,1) computed from it. (R13, unchanged)
// ----------------------------------------------------------------------------
#define NPW 68
#define NP_SMEM_BYTES (128 * NPW * 4)

__global__ void __launch_bounds__(256, 2) node_proj_mma_kernel(
    const float* __restrict__ x, int n_nodes)
{
    extern __shared__ uint32_t As[];               // [128 m][68 w] fp16x2

    const int tid  = threadIdx.x;
    const int wid  = tid >> 5;
    const int lane = tid & 31;
    const int g    = lane >> 2;
    const int tq   = lane & 3;
    const int wm   = wid >> 2;
    const int wn   = wid & 3;

    const int bm = blockIdx.x * 128;

#pragma unroll
    for (int p = 0; p < 8; p++) {
        int idx = tid + p * 256;
        int r   = idx >> 4;
        int q   = idx & 15;
        int grow = bm + r;
        float4 v0 = make_float4(0.f, 0.f, 0.f, 0.f);
        float4 v1 = v0;
        if (grow < n_nodes) {
            const float* xr = x + (size_t)grow * HID + q * 8;
            v0 = *(const float4*)xr;
            v1 = *(const float4*)(xr + 4);
        }
        uint4 t;
        t.x = h2_as_u32(__floats2half2_rn(v0.x, v0.y));
        t.y = h2_as_u32(__floats2half2_rn(v0.z, v0.w));
        t.z = h2_as_u32(__floats2half2_rn(v1.x, v1.y));
        t.w = h2_as_u32(__floats2half2_rn(v1.z, v1.w));
        *(uint4*)(As + r * NPW + q * 4) = t;
    }
    __syncthreads();

    const uint32_t* Ab = As + (wm * 64 + g) * NPW + tq;

#pragma unroll
    for (int o = 0; o < 2; o++) {
        float acc[4][4][4];
#pragma unroll
        for (int a = 0; a < 4; a++)
#pragma unroll
            for (int b = 0; b < 4; b++)
#pragma unroll
                for (int c = 0; c < 4; c++) acc[a][b][c] = 0.f;

        const uint2* __restrict__ wf_base =
            g_W1fh + ((size_t)o * 8 * 16 + wn * 4) * 32 + lane;

#pragma unroll
        for (int kc = 0; kc < 8; kc++) {
            uint2 bfr[4];
            const uint2* wf = wf_base + (size_t)kc * 16 * 32;
#pragma unroll
            for (int nf = 0; nf < 4; nf++) bfr[nf] = wf[nf * 32];

            uint32_t afr[4][4];
#pragma unroll
            for (int mf = 0; mf < 4; mf++) {
                const uint32_t* ap = Ab + mf * 16 * NPW + kc * 8;
                afr[mf][0] = ap[0];
                afr[mf][1] = ap[8 * NPW];
                afr[mf][2] = ap[4];
                afr[mf][3] = ap[8 * NPW + 4];
            }
#pragma unroll
            for (int mf = 0; mf < 4; mf++)
#pragma unroll
                for (int nf = 0; nf < 4; nf++)
                    mma_f16(acc[mf][nf], afr[mf], bfr[nf].x, bfr[nf].y);
        }

#pragma unroll
        for (int mf = 0; mf < 4; mf++) {
            int r0g = bm + wm * 64 + mf * 16 + g;
#pragma unroll
            for (int nf = 0; nf < 4; nf++) {
                int col = o * 128 + wn * 32 + nf * 8 + 2 * tq;
                if (r0g < n_nodes)
                    *(__half2*)(g_Ph + (size_t)r0g * 256 + col) =
                        __floats2half2_rn(acc[mf][nf][0], acc[mf][nf][1]);
                if (r0g + 8 < n_nodes)
                    *(__half2*)(g_Ph + (size_t)(r0g + 8) * 256 + col) =
                        __floats2half2_rn(acc[mf][nf][2], acc[mf][nf][3]);
            }
        }
    }
}

// ----------------------------------------------------------------------------
// Kernel 2: edge MLP. 8 warps/block, 32-edge tiles/warp with K-SPLIT staging:
// h computed & MMA'd in two 64-k halves so hbuf stays 4.6KB/warp (32 warps/SM
// retained) while every W2 B-fragment load now feeds TWO m16 subtiles.
// Gather: LDG.64, 2 edges/iter. A-frags via ldmatrix.x4 (stride 36 words,
// conflict-free). kc order 0..7 ascending -> accumulation order unchanged.
// ----------------------------------------------------------------------------
#define EWARPS 8
#define ETHREADS (EWARPS * 32)
#define ETILE 32
#define EW 36                            // words per hbuf row (32 data + 4 pad)
#define HBUF_WORDS (ETILE * EW)          // 1152 words = 4608 B
#define W2F_BYTES 8192
#define SM_BW   (W2F_BYTES)              // 32 float2 = 256 B
#define SM_WCBB (W2F_BYTES + 256)        // 32 uint4 = 512 B
#define SM_HB   (W2F_BYTES + 256 + 512)
#define EDGE_SMEM_BYTES (SM_HB + EWARPS * HBUF_WORDS * 4)

__global__ void __launch_bounds__(ETHREADS, 4) edge_mlp_kernel(
    const int*   __restrict__ edge_index,   // [2*E]: src then dst
    const float* __restrict__ eattr,        // [E]
    const float* __restrict__ W1,           // [257*128], row 256 = w1c
    const float* __restrict__ b1,           // [128]
    const float* __restrict__ W2,           // [128*32]
    const float* __restrict__ b2,           // [32]
    const float* __restrict__ W3,           // [32]
    const float* __restrict__ b3,           // [1]
    float*       __restrict__ out,          // [E]
    int n_edges)
{
    extern __shared__ char smem[];
    uint32_t* __restrict__ w2f   = (uint32_t*)smem;                 // ldmatrix-packed
    float2*   __restrict__ s_bw  = (float2*)(smem + SM_BW);         // {b2, w3}[32]
    uint4*    __restrict__ s_wcbb = (uint4*)(smem + SM_WCBB);       // [2][16]
    uint32_t* __restrict__ hb_all = (uint32_t*)(smem + SM_HB);

    const int tid  = threadIdx.x;
    const int wid  = tid >> 5;
    const int lane = tid & 31;
    const int g    = lane >> 2;
    const int tq   = lane & 3;
    const int hl   = lane >> 4;          // which of 2 edges per gather iter
    const int l16  = lane & 15;
    uint32_t* __restrict__ hbuf = hb_all + wid * HBUF_WORDS;

    // --- pack W2 into ldmatrix row order (identical to R14) ---
    for (int i = tid; i < 2048; i += ETHREADS) {
        int kc = i >> 8;
        int m  = (i >> 5) & 7;
        int gg = (i >> 2) & 7;
        int ep = i & 3;
        int nt = m >> 1, hb = m & 1;
        int k  = kc * 16 + hb * 8 + 2 * ep;
        int col = nt * 8 + gg;
        __half2 v = __floats2half2_rn(W2[k * 32 + col], W2[(k + 1) * 32 + col]);
        w2f[i] = h2_as_u32(v);
    }
    if (tid < 32) s_bw[tid] = make_float2(b2[tid], W3[tid]);
    // layer-1 constants: for half h, lane l16 covers halves h*64+4*l16..+3
    if (tid < 32) {
        int h = tid >> 4, l = tid & 15;
        int c = h * 64 + 4 * l;
        const float* wrow = W1 + 256 * HID + c;
        uint4 v;
        v.x = h2_as_u32(__floats2half2_rn(wrow[0], wrow[1]));
        v.y = h2_as_u32(__floats2half2_rn(wrow[2], wrow[3]));
        v.z = h2_as_u32(__floats2half2_rn(b1[c],     b1[c + 1]));
        v.w = h2_as_u32(__floats2half2_rn(b1[c + 2], b1[c + 3]));
        s_wcbb[tid] = v;
    }
    __syncthreads();

    const __half2 zero2 = __floats2half2_rn(0.f, 0.f);
    const float  b3v = b3[0];

    // ldmatrix base addresses
    const uint32_t hb_smem = (uint32_t)__cvta_generic_to_shared(hbuf);
    const uint32_t lmA_base = hb_smem + (uint32_t)l16 * (EW * 4) + (uint32_t)hl * 16;
    const uint32_t w2_smem = (uint32_t)__cvta_generic_to_shared(w2f);
    const uint32_t lmB_base = w2_smem + (uint32_t)lane * 16;

    const int* __restrict__ src = edge_index;
    const int* __restrict__ dst = edge_index + n_edges;

    const int gw = blockIdx.x * EWARPS + wid;
    const int nwarps = gridDim.x * EWARPS;
    const int ntiles = (n_edges + ETILE - 1) / ETILE;

    for (int t = gw; t < ntiles; t += nwarps) {
        const int base = t * ETILE;

        // ---- stage edge data: every lane owns one of the 32 edges ----
        int sE = 0, dE = 0;
        float eaE = 0.f;
        {
            int e = base + lane;
            if (e < n_edges) { sE = src[e]; dE = dst[e]; eaE = eattr[e]; }
        }

        float dacc[2][4][4];
#pragma unroll
        for (int st = 0; st < 2; st++)
#pragma unroll
            for (int nt = 0; nt < 4; nt++)
#pragma unroll
                for (int j = 0; j < 4; j++) dacc[st][nt][j] = 0.f;

#pragma unroll
        for (int h = 0; h < 2; h++) {
            // per-half layer-1 constants (1 LDS.128)
            uint4 wb = s_wcbb[h * 16 + l16];
            const __half2 wc0 = u32_as_h2(wb.x);
            const __half2 wc1 = u32_as_h2(wb.y);
            const __half2 bb0 = u32_as_h2(wb.z);
            const __half2 bb1v = u32_as_h2(wb.w);
            const int hofs = h << 6;   // half offset in halves

            // ---- gather + relu for this k-half (LDG.64, 2 edges/iter) ----
#pragma unroll
            for (int it = 0; it < 16; it++) {
                const int rr = 2 * it + hl;
                int   s  = __shfl_sync(0xffffffffu, sE, rr);
                int   dd = __shfl_sync(0xffffffffu, dE, rr);
                float ea = __shfl_sync(0xffffffffu, eaE, rr);
                __half2 ea2 = __float2half2_rn(ea);
                uint2 ua = *(const uint2*)(g_Ph + (size_t)s  * 256 + hofs + 4 * l16);
                uint2 ub = *(const uint2*)(g_Ph + (size_t)dd * 256 + 128 + hofs + 4 * l16);
                __half2 hh;
                uint2 hv;
                hh = __hadd2(__hadd2(u32_as_h2(ua.x), u32_as_h2(ub.x)), bb0);
                hv.x = h2_as_u32(__hmax2(__hfma2(ea2, wc0, hh), zero2));
                hh = __hadd2(__hadd2(u32_as_h2(ua.y), u32_as_h2(ub.y)), bb1v);
                hv.y = h2_as_u32(__hmax2(__hfma2(ea2, wc1, hh), zero2));
                *(uint2*)(hbuf + rr * EW + 2 * l16) = hv;
            }
            __syncwarp();

            // ---- mma for this half: kc = 4h..4h+3; B shared by 2 subtiles ----
#pragma unroll
            for (int kk = 0; kk < 4; kk++) {
                const int kc = h * 4 + kk;
                uint32_t b01[4], b23[4];
                ldmatrix_x4(b01, lmB_base + (uint32_t)kc * 1024);
                ldmatrix_x4(b23, lmB_base + (uint32_t)kc * 1024 + 512);
#pragma unroll
                for (int st = 0; st < 2; st++) {
                    uint32_t a[4];
                    ldmatrix_x4(a, lmA_base + (uint32_t)st * (16 * EW * 4)
                                            + (uint32_t)kk * 32);
                    mma_f16(dacc[st][0], a, b01[0], b01[1]);
                    mma_f16(dacc[st][1], a, b01[2], b01[3]);
                    mma_f16(dacc[st][2], a, b23[0], b23[1]);
                    mma_f16(dacc[st][3], a, b23[2], b23[3]);
                }
            }
            __syncwarp();   // hbuf safe before next half / next tile
        }

        // ---- layer 3: +b2, relu, *W3, quad-reduce, sigmoid ----
#pragma unroll
        for (int st = 0; st < 2; st++) {
            float acc0 = 0.f, acc1 = 0.f;
#pragma unroll
            for (int nt = 0; nt < 4; nt++) {
#pragma unroll
                for (int i = 0; i < 2; i++) {
                    int col = nt * 8 + 2 * tq + i;
                    float2 bw = s_bw[col];
                    acc0 = fmaf(fmaxf(dacc[st][nt][i]     + bw.x, 0.f), bw.y, acc0);
                    acc1 = fmaf(fmaxf(dacc[st][nt][2 + i] + bw.x, 0.f), bw.y, acc1);
                }
            }
            acc0 += __shfl_xor_sync(0xffffffffu, acc0, 1);
            acc0 += __shfl_xor_sync(0xffffffffu, acc0, 2);
            acc1 += __shfl_xor_sync(0xffffffffu, acc1, 1);
            acc1 += __shfl_xor_sync(0xffffffffu, acc1, 2);
            if (tq == 0) {
                int e0 = base + st * 16 + g;
                int e1 = e0 + 8;
                if (e0 < n_edges) {
                    float z = acc0 + b3v;
                    out[e0] = 1.f / (1.f + __expf(-z));
                }
                if (e1 < n_edges) {
                    float z = acc1 + b3v;
                    out[e1] = 1.f / (1.f + __expf(-z));
                }
            }
        }
    }
}

// ----------------------------------------------------------------------------
// Launch
// ----------------------------------------------------------------------------
extern "C" void kernel_launch(void* const* d_in, const int* in_sizes, int n_in,
                              void* d_out, int out_size)
{
    const float* x  = (const float*)d_in[0];
    const int*   ei = (const int*)d_in[1];
    const float* ea = (const float*)d_in[2];
    const float* W1 = (const float*)d_in[3];
    const float* b1 = (const float*)d_in[4];
    const float* W2 = (const float*)d_in[5];
    const float* b2 = (const float*)d_in[6];
    const float* W3 = (const float*)d_in[7];
    const float* b3 = (const float*)d_in[8];
    float*       out = (float*)d_out;

    const int n_nodes = in_sizes[0] / HID;     // 100000
    const int n_edges = in_sizes[2];           // 1000000

    static int smem_set = 0;
    if (!smem_set) {
        cudaFuncSetAttribute(node_proj_mma_kernel,
                             cudaFuncAttributeMaxDynamicSharedMemorySize, NP_SMEM_BYTES);
        cudaFuncSetAttribute(edge_mlp_kernel,
                             cudaFuncAttributeMaxDynamicSharedMemorySize, EDGE_SMEM_BYTES);
        smem_set = 1;
    }

    // Kernel 0: pack W1 fragments (L2-hot afterwards)
    pack_w1_kernel<<<32, 256>>>(W1);

    // Kernel 1: node projections (both halves per block, x read once)
    const int g1 = (n_nodes + 127) / 128;
    node_proj_mma_kernel<<<g1, 256, NP_SMEM_BYTES>>>(x, n_nodes);

    // Kernel 2: edge MLP (32-edge k-split tiles, shared B-frags, 32 warps/SM)
    const int blocks = 592;
    edge_mlp_kernel<<<blocks, ETHREADS, EDGE_SMEM_BYTES>>>(
        ei, ea, W1, b1, W2, b2, W3, b3, out, n_edges);
}

// round 16
// speedup vs baseline: 1.1110x; 1.1110x over previous
#include <cuda_runtime.h>
#include <cuda_fp16.h>
#include <cstdint>

#define HID 128
#define NNODES 100000

// Node projections, fp16: P[node][0:128] = x@W1[0:128], [128:256] = x@W1[128:256]
__device__ __half g_Ph[(size_t)NNODES * 256];
// W1 packed into fp16 m16n8k16 B-fragment order: [2 halves][8 kc][16 nf][32 lanes] uint2
__device__ uint2 g_W1fh[2 * 8 * 16 * 32];

// ----------------------------------------------------------------------------
// mma helpers (portable: sm_103 PTX target has no tcgen05)
// ----------------------------------------------------------------------------
__device__ __forceinline__ void mma_f16(float* d, const uint32_t* a, uint32_t b0, uint32_t b1) {
    asm volatile(
        "mma.sync.aligned.m16n8k16.row.col.f32.f16.f16.f32 "
        "{%0,%1,%2,%3}, {%4,%5,%6,%7}, {%8,%9}, {%0,%1,%2,%3};"
        : "+f"(d[0]), "+f"(d[1]), "+f"(d[2]), "+f"(d[3])
        : "r"(a[0]), "r"(a[1]), "r"(a[2]), "r"(a[3]), "r"(b0), "r"(b1));
}

__device__ __forceinline__ void ldmatrix_x4(uint32_t* r, uint32_t smem_addr) {
    asm volatile(
        "ldmatrix.sync.aligned.m8n8.x4.shared.b16 {%0,%1,%2,%3}, [%4];"
        : "=r"(r[0]), "=r"(r[1]), "=r"(r[2]), "=r"(r[3])
        : "r"(smem_addr));
}

__device__ __forceinline__ uint32_t h2_as_u32(__half2 h) {
    uint32_t u;
    memcpy(&u, &h, 4);
    return u;
}
__device__ __forceinline__ __half2 u32_as_h2(uint32_t u) {
    __half2 h;
    memcpy(&h, &u, 4);
    return h;
}

// ----------------------------------------------------------------------------
// Kernel 0: pack W1 into fp16 m16n8k16 B-fragment order (once; 64KB, L2-hot).
// ----------------------------------------------------------------------------
__global__ void pack_w1_kernel(const float* __restrict__ W1)
{
    int i = blockIdx.x * blockDim.x + threadIdx.x;
    if (i >= 2 * 8 * 16 * 32) return;
    int o  = i >> 12;
    int kc = (i >> 9) & 7;
    int nf = (i >> 5) & 15;
    int ln = i & 31;
    int g  = ln >> 2, tq = ln & 3;
    int n  = nf * 8 + g;
    int k0 = o * 128 + kc * 16 + 2 * tq;
    __half2 b0 = __floats2half2_rn(W1[(size_t)k0 * HID + n],       W1[(size_t)(k0 + 1) * HID + n]);
    __half2 b1 = __floats2half2_rn(W1[(size_t)(k0 + 8) * HID + n], W1[(size_t)(k0 + 9) * HID + n]);
    g_W1fh[i] = make_uint2(h2_as_u32(b0), h2_as_u32(b1));
}

// ----------------------------------------------------------------------------
// Kernel 1: node projection via fp16 mma. Full K=128 A-tile resident in smem
// (staged ONCE), then both W halves (o=0,1) computed from it. (R13, unchanged)
// ----------------------------------------------------------------------------
#define NPW 68
#define NP_SMEM_BYTES (128 * NPW * 4)

__global__ void __launch_bounds__(256, 2) node_proj_mma_kernel(
    const float* __restrict__ x, int n_nodes)
{
    extern __shared__ uint32_t As[];               // [128 m][68 w] fp16x2

    const int tid  = threadIdx.x;
    const int wid  = tid >> 5;
    const int lane = tid & 31;
    const int g    = lane >> 2;
    const int tq   = lane & 3;
    const int wm   = wid >> 2;
    const int wn   = wid & 3;

    const int bm = blockIdx.x * 128;

#pragma unroll
    for (int p = 0; p < 8; p++) {
        int idx = tid + p * 256;
        int r   = idx >> 4;
        int q   = idx & 15;
        int grow = bm + r;
        float4 v0 = make_float4(0.f, 0.f, 0.f, 0.f);
        float4 v1 = v0;
        if (grow < n_nodes) {
            const float* xr = x + (size_t)grow * HID + q * 8;
            v0 = *(const float4*)xr;
            v1 = *(const float4*)(xr + 4);
        }
        uint4 t;
        t.x = h2_as_u32(__floats2half2_rn(v0.x, v0.y));
        t.y = h2_as_u32(__floats2half2_rn(v0.z, v0.w));
        t.z = h2_as_u32(__floats2half2_rn(v1.x, v1.y));
        t.w = h2_as_u32(__floats2half2_rn(v1.z, v1.w));
        *(uint4*)(As + r * NPW + q * 4) = t;
    }
    __syncthreads();

    const uint32_t* Ab = As + (wm * 64 + g) * NPW + tq;

#pragma unroll
    for (int o = 0; o < 2; o++) {
        float acc[4][4][4];
#pragma unroll
        for (int a = 0; a < 4; a++)
#pragma unroll
            for (int b = 0; b < 4; b++)
#pragma unroll
                for (int c = 0; c < 4; c++) acc[a][b][c] = 0.f;

        const uint2* __restrict__ wf_base =
            g_W1fh + ((size_t)o * 8 * 16 + wn * 4) * 32 + lane;

#pragma unroll
        for (int kc = 0; kc < 8; kc++) {
            uint2 bfr[4];
            const uint2* wf = wf_base + (size_t)kc * 16 * 32;
#pragma unroll
            for (int nf = 0; nf < 4; nf++) bfr[nf] = wf[nf * 32];

            uint32_t afr[4][4];
#pragma unroll
            for (int mf = 0; mf < 4; mf++) {
                const uint32_t* ap = Ab + mf * 16 * NPW + kc * 8;
                afr[mf][0] = ap[0];
                afr[mf][1] = ap[8 * NPW];
                afr[mf][2] = ap[4];
                afr[mf][3] = ap[8 * NPW + 4];
            }
#pragma unroll
            for (int mf = 0; mf < 4; mf++)
#pragma unroll
                for (int nf = 0; nf < 4; nf++)
                    mma_f16(acc[mf][nf], afr[mf], bfr[nf].x, bfr[nf].y);
        }

#pragma unroll
        for (int mf = 0; mf < 4; mf++) {
            int r0g = bm + wm * 64 + mf * 16 + g;
#pragma unroll
            for (int nf = 0; nf < 4; nf++) {
                int col = o * 128 + wn * 32 + nf * 8 + 2 * tq;
                if (r0g < n_nodes)
                    *(__half2*)(g_Ph + (size_t)r0g * 256 + col) =
                        __floats2half2_rn(acc[mf][nf][0], acc[mf][nf][1]);
                if (r0g + 8 < n_nodes)
                    *(__half2*)(g_Ph + (size_t)(r0g + 8) * 256 + col) =
                        __floats2half2_rn(acc[mf][nf][2], acc[mf][nf][3]);
            }
        }
    }
}

// ----------------------------------------------------------------------------
// Kernel 2: edge MLP (R14 configuration — best measured). 8 warps/block,
// 16-edge tiles/warp, LDG.128 gather (2 edges/iter), A-frags via ldmatrix.x4,
// B-frags via ldmatrix.x4 (w2f packed in ldmatrix row order), next-tile edge
// index prefetch under the MMA. Epilogue {b2,w3} fused to one float2 table.
// ----------------------------------------------------------------------------
#define EWARPS 8
#define ETHREADS (EWARPS * 32)
#define HS 136                          // halves per hbuf row (68 words)
#define HBUF_WORDS (16 * (HS / 2))
#define W2F_BYTES 8192
#define EDGE_SMEM_BYTES (W2F_BYTES + 256 + EWARPS * HBUF_WORDS * 4)

__global__ void __launch_bounds__(ETHREADS, 4) edge_mlp_kernel(
    const int*   __restrict__ edge_index,   // [2*E]: src then dst
    const float* __restrict__ eattr,        // [E]
    const float* __restrict__ W1,           // [257*128], row 256 = w1c
    const float* __restrict__ b1,           // [128]
    const float* __restrict__ W2,           // [128*32]
    const float* __restrict__ b2,           // [32]
    const float* __restrict__ W3,           // [32]
    const float* __restrict__ b3,           // [1]
    float*       __restrict__ out,          // [E]
    int n_edges)
{
    extern __shared__ char smem[];
    uint32_t* __restrict__ w2f = (uint32_t*)smem;                  // ldmatrix-packed
    float2* __restrict__ s_bw = (float2*)(smem + W2F_BYTES);       // {b2,w3}[32]
    uint32_t* __restrict__ hb_all = (uint32_t*)(smem + W2F_BYTES + 256);

    const int tid  = threadIdx.x;
    const int wid  = tid >> 5;
    const int lane = tid & 31;
    const int g    = lane >> 2;
    const int tq   = lane & 3;
    const int hl   = lane >> 4;          // half-warp: which of 2 edges per iter
    const int l16  = lane & 15;
    uint32_t* __restrict__ hbuf = hb_all + wid * HBUF_WORDS;

    // --- pack W2 into ldmatrix row order ---
    // word i = [kc(8)][m(8)][g(8)][ep(4)]; m = nt*2 + hb.
    // matrix M[g][e] = W2[kc*16 + hb*8 + e][nt*8 + g], words pack e pairs.
    for (int i = tid; i < 2048; i += ETHREADS) {
        int kc = i >> 8;
        int m  = (i >> 5) & 7;
        int gg = (i >> 2) & 7;
        int ep = i & 3;
        int nt = m >> 1, hb = m & 1;
        int k  = kc * 16 + hb * 8 + 2 * ep;
        int col = nt * 8 + gg;
        __half2 v = __floats2half2_rn(W2[k * 32 + col], W2[(k + 1) * 32 + col]);
        w2f[i] = h2_as_u32(v);
    }
    if (tid < 32) s_bw[tid] = make_float2(b2[tid], W3[tid]);
    __syncthreads();

    // --- per-lane layer-1 constants: this lane handles h cols c8..c8+7 ---
    const int c8 = l16 * 8;
    __half2 wc[4], bb[4];
    {
        const float* wrow = W1 + 256 * HID + c8;
#pragma unroll
        for (int j = 0; j < 4; j++) {
            wc[j] = __floats2half2_rn(wrow[2 * j], wrow[2 * j + 1]);
            bb[j] = __floats2half2_rn(b1[c8 + 2 * j], b1[c8 + 2 * j + 1]);
        }
    }
    const __half2 zero2 = __floats2half2_rn(0.f, 0.f);
    const float  b3v = b3[0];

    // ldmatrix base addresses
    const uint32_t hb_smem = (uint32_t)__cvta_generic_to_shared(hbuf);
    const uint32_t lmA_base = hb_smem + (uint32_t)l16 * (HS / 2) * 4 + (uint32_t)hl * 16;
    const uint32_t w2_smem = (uint32_t)__cvta_generic_to_shared(w2f);
    const uint32_t lmB_base = w2_smem + (uint32_t)lane * 16;

    const int* __restrict__ src = edge_index;
    const int* __restrict__ dst = edge_index + n_edges;

    const int gw = blockIdx.x * EWARPS + wid;
    const int nwarps = gridDim.x * EWARPS;
    const int ntiles = (n_edges + 15) >> 4;

    // ---- prologue: stage first tile's edge data ----
    int sA = 0, dA = 0;
    float eaA = 0.f;
    if (lane < 16 && gw < ntiles) {
        int e = (gw << 4) + lane;
        if (e < n_edges) { sA = src[e]; dA = dst[e]; eaA = eattr[e]; }
    }

    for (int t = gw; t < ntiles; t += nwarps) {
        const int base = t << 4;

        // ---- layer 1: LDG.128 gather, 2 edges per iteration ----
#pragma unroll
        for (int it = 0; it < 8; it++) {
            const int rr = 2 * it + hl;
            int   s  = __shfl_sync(0xffffffffu, sA, rr);
            int   dd = __shfl_sync(0xffffffffu, dA, rr);
            float ea = __shfl_sync(0xffffffffu, eaA, rr);
            __half2 ea2 = __float2half2_rn(ea);
            uint4 ua = *(const uint4*)(g_Ph + (size_t)s  * 256 + c8);
            uint4 ub = *(const uint4*)(g_Ph + (size_t)dd * 256 + 128 + c8);
            uint4 hv;
            {
                __half2 h;
                h = __hadd2(__hadd2(u32_as_h2(ua.x), u32_as_h2(ub.x)), bb[0]);
                hv.x = h2_as_u32(__hmax2(__hfma2(ea2, wc[0], h), zero2));
                h = __hadd2(__hadd2(u32_as_h2(ua.y), u32_as_h2(ub.y)), bb[1]);
                hv.y = h2_as_u32(__hmax2(__hfma2(ea2, wc[1], h), zero2));
                h = __hadd2(__hadd2(u32_as_h2(ua.z), u32_as_h2(ub.z)), bb[2]);
                hv.z = h2_as_u32(__hmax2(__hfma2(ea2, wc[2], h), zero2));
                h = __hadd2(__hadd2(u32_as_h2(ua.w), u32_as_h2(ub.w)), bb[3]);
                hv.w = h2_as_u32(__hmax2(__hfma2(ea2, wc[3], h), zero2));
            }
            *(uint4*)(hbuf + rr * (HS / 2) + (c8 >> 1)) = hv;
        }
        __syncwarp();

        // ---- prefetch next tile's edge indices (hidden under MMA) ----
        int sN = 0, dN = 0;
        float eaN = 0.f;
        {
            int t2 = t + nwarps;
            if (lane < 16 && t2 < ntiles) {
                int e = (t2 << 4) + lane;
                if (e < n_edges) { sN = src[e]; dN = dst[e]; eaN = eattr[e]; }
            }
        }

        // ---- layer 2: fp16 mma; A and B both via ldmatrix.x4 ----
        float dacc[4][4];
#pragma unroll
        for (int nt = 0; nt < 4; nt++)
#pragma unroll
            for (int j = 0; j < 4; j++) dacc[nt][j] = 0.f;

#pragma unroll
        for (int kc = 0; kc < 8; kc++) {
            uint32_t a[4];
            ldmatrix_x4(a, lmA_base + (uint32_t)kc * 32);
            uint32_t b01[4], b23[4];
            ldmatrix_x4(b01, lmB_base + (uint32_t)kc * 1024);
            ldmatrix_x4(b23, lmB_base + (uint32_t)kc * 1024 + 512);
            mma_f16(dacc[0], a, b01[0], b01[1]);
            mma_f16(dacc[1], a, b01[2], b01[3]);
            mma_f16(dacc[2], a, b23[0], b23[1]);
            mma_f16(dacc[3], a, b23[2], b23[3]);
        }
        __syncwarp();   // hbuf safe before next tile overwrites

        // ---- layer 3: +b2, relu, *W3, quad-reduce, sigmoid ----
        float acc0 = 0.f, acc1 = 0.f;   // rows base+g and base+g+8
#pragma unroll
        for (int nt = 0; nt < 4; nt++) {
#pragma unroll
            for (int i = 0; i < 2; i++) {
                int col = nt * 8 + 2 * tq + i;
                float2 bw = s_bw[col];
                acc0 = fmaf(fmaxf(dacc[nt][i]     + bw.x, 0.f), bw.y, acc0);
                acc1 = fmaf(fmaxf(dacc[nt][2 + i] + bw.x, 0.f), bw.y, acc1);
            }
        }
        acc0 += __shfl_xor_sync(0xffffffffu, acc0, 1);
        acc0 += __shfl_xor_sync(0xffffffffu, acc0, 2);
        acc1 += __shfl_xor_sync(0xffffffffu, acc1, 1);
        acc1 += __shfl_xor_sync(0xffffffffu, acc1, 2);
        if (tq == 0) {
            int e0 = base + g;
            int e1 = base + g + 8;
            if (e0 < n_edges) {
                float z = acc0 + b3v;
                out[e0] = 1.f / (1.f + __expf(-z));
            }
            if (e1 < n_edges) {
                float z = acc1 + b3v;
                out[e1] = 1.f / (1.f + __expf(-z));
            }
        }

        sA = sN; dA = dN; eaA = eaN;
    }
}

// ----------------------------------------------------------------------------
// Launch
// ----------------------------------------------------------------------------
extern "C" void kernel_launch(void* const* d_in, const int* in_sizes, int n_in,
                              void* d_out, int out_size)
{
    const float* x  = (const float*)d_in[0];
    const int*   ei = (const int*)d_in[1];
    const float* ea = (const float*)d_in[2];
    const float* W1 = (const float*)d_in[3];
    const float* b1 = (const float*)d_in[4];
    const float* W2 = (const float*)d_in[5];
    const float* b2 = (const float*)d_in[6];
    const float* W3 = (const float*)d_in[7];
    const float* b3 = (const float*)d_in[8];
    float*       out = (float*)d_out;

    const int n_nodes = in_sizes[0] / HID;     // 100000
    const int n_edges = in_sizes[2];           // 1000000

    static int smem_set = 0;
    if (!smem_set) {
        cudaFuncSetAttribute(node_proj_mma_kernel,
                             cudaFuncAttributeMaxDynamicSharedMemorySize, NP_SMEM_BYTES);
        cudaFuncSetAttribute(edge_mlp_kernel,
                             cudaFuncAttributeMaxDynamicSharedMemorySize, EDGE_SMEM_BYTES);
        smem_set = 1;
    }

    // Kernel 0: pack W1 fragments (L2-hot afterwards)
    pack_w1_kernel<<<32, 256>>>(W1);

    // Kernel 1: node projections (both halves per block, x read once)
    const int g1 = (n_nodes + 127) / 128;
    node_proj_mma_kernel<<<g1, 256, NP_SMEM_BYTES>>>(x, n_nodes);

    // Kernel 2: edge MLP (R14 config: ldmatrix A+B, LDG.128 gather, prefetch)
    const int blocks = 592;
    edge_mlp_kernel<<<blocks, ETHREADS, EDGE_SMEM_BYTES>>>(
        ei, ea, W1, b1, W2, b2, W3, b3, out, n_edges);
}

// round 17
// speedup vs baseline: 1.1449x; 1.0305x over previous
#include <cuda_runtime.h>
#include <cuda_fp16.h>
#include <cstdint>

#define HID 128
#define NNODES 100000

// Node projections, fp16: P[node][0:128] = x@W1[0:128], [128:256] = x@W1[128:256]
__device__ __half g_Ph[(size_t)NNODES * 256];
// W1 packed into fp16 m16n8k16 B-fragment order: [2 halves][8 kc][16 nf][32 lanes] uint2
__device__ uint2 g_W1fh[2 * 8 * 16 * 32];

// ----------------------------------------------------------------------------
// mma helpers (portable: sm_103 PTX target has no tcgen05)
// ----------------------------------------------------------------------------
__device__ __forceinline__ void mma_f16(float* d, const uint32_t* a, uint32_t b0, uint32_t b1) {
    asm volatile(
        "mma.sync.aligned.m16n8k16.row.col.f32.f16.f16.f32 "
        "{%0,%1,%2,%3}, {%4,%5,%6,%7}, {%8,%9}, {%0,%1,%2,%3};"
        : "+f"(d[0]), "+f"(d[1]), "+f"(d[2]), "+f"(d[3])
        : "r"(a[0]), "r"(a[1]), "r"(a[2]), "r"(a[3]), "r"(b0), "r"(b1));
}

__device__ __forceinline__ void ldmatrix_x4(uint32_t* r, uint32_t smem_addr) {
    asm volatile(
        "ldmatrix.sync.aligned.m8n8.x4.shared.b16 {%0,%1,%2,%3}, [%4];"
        : "=r"(r[0]), "=r"(r[1]), "=r"(r[2]), "=r"(r[3])
        : "r"(smem_addr));
}

__device__ __forceinline__ uint32_t h2_as_u32(__half2 h) {
    uint32_t u;
    memcpy(&u, &h, 4);
    return u;
}
__device__ __forceinline__ __half2 u32_as_h2(uint32_t u) {
    __half2 h;
    memcpy(&h, &u, 4);
    return h;
}

// ----------------------------------------------------------------------------
// Kernel 0: pack W1 into fp16 m16n8k16 B-fragment order (once; 64KB, L2-hot).
// ----------------------------------------------------------------------------
__global__ void pack_w1_kernel(const float* __restrict__ W1)
{
    int i = blockIdx.x * blockDim.x + threadIdx.x;
    if (i >= 2 * 8 * 16 * 32) return;
    int o  = i >> 12;
    int kc = (i >> 9) & 7;
    int nf = (i >> 5) & 15;
    int ln = i & 31;
    int g  = ln >> 2, tq = ln & 3;
    int n  = nf * 8 + g;
    int k0 = o * 128 + kc * 16 + 2 * tq;
    __half2 b0 = __floats2half2_rn(W1[(size_t)k0 * HID + n],       W1[(size_t)(k0 + 1) * HID + n]);
    __half2 b1 = __floats2half2_rn(W1[(size_t)(k0 + 8) * HID + n], W1[(size_t)(k0 + 9) * HID + n]);
    g_W1fh[i] = make_uint2(h2_as_u32(b0), h2_as_u32(b1));
}

// ----------------------------------------------------------------------------
// Kernel 1: node projection via fp16 mma. Full K=128 A-tile resident in smem
// (staged ONCE), then both W halves (o=0,1) computed from it. (R13, unchanged)
// ----------------------------------------------------------------------------
#define NPW 68
#define NP_SMEM_BYTES (128 * NPW * 4)

__global__ void __launch_bounds__(256, 2) node_proj_mma_kernel(
    const float* __restrict__ x, int n_nodes)
{
    extern __shared__ uint32_t As[];               // [128 m][68 w] fp16x2

    const int tid  = threadIdx.x;
    const int wid  = tid >> 5;
    const int lane = tid & 31;
    const int g    = lane >> 2;
    const int tq   = lane & 3;
    const int wm   = wid >> 2;
    const int wn   = wid & 3;

    const int bm = blockIdx.x * 128;

#pragma unroll
    for (int p = 0; p < 8; p++) {
        int idx = tid + p * 256;
        int r   = idx >> 4;
        int q   = idx & 15;
        int grow = bm + r;
        float4 v0 = make_float4(0.f, 0.f, 0.f, 0.f);
        float4 v1 = v0;
        if (grow < n_nodes) {
            const float* xr = x + (size_t)grow * HID + q * 8;
            v0 = *(const float4*)xr;
            v1 = *(const float4*)(xr + 4);
        }
        uint4 t;
        t.x = h2_as_u32(__floats2half2_rn(v0.x, v0.y));
        t.y = h2_as_u32(__floats2half2_rn(v0.z, v0.w));
        t.z = h2_as_u32(__floats2half2_rn(v1.x, v1.y));
        t.w = h2_as_u32(__floats2half2_rn(v1.z, v1.w));
        *(uint4*)(As + r * NPW + q * 4) = t;
    }
    __syncthreads();

    const uint32_t* Ab = As + (wm * 64 + g) * NPW + tq;

#pragma unroll
    for (int o = 0; o < 2; o++) {
        float acc[4][4][4];
#pragma unroll
        for (int a = 0; a < 4; a++)
#pragma unroll
            for (int b = 0; b < 4; b++)
#pragma unroll
                for (int c = 0; c < 4; c++) acc[a][b][c] = 0.f;

        const uint2* __restrict__ wf_base =
            g_W1fh + ((size_t)o * 8 * 16 + wn * 4) * 32 + lane;

#pragma unroll
        for (int kc = 0; kc < 8; kc++) {
            uint2 bfr[4];
            const uint2* wf = wf_base + (size_t)kc * 16 * 32;
#pragma unroll
            for (int nf = 0; nf < 4; nf++) bfr[nf] = wf[nf * 32];

            uint32_t afr[4][4];
#pragma unroll
            for (int mf = 0; mf < 4; mf++) {
                const uint32_t* ap = Ab + mf * 16 * NPW + kc * 8;
                afr[mf][0] = ap[0];
                afr[mf][1] = ap[8 * NPW];
                afr[mf][2] = ap[4];
                afr[mf][3] = ap[8 * NPW + 4];
            }
#pragma unroll
            for (int mf = 0; mf < 4; mf++)
#pragma unroll
                for (int nf = 0; nf < 4; nf++)
                    mma_f16(acc[mf][nf], afr[mf], bfr[nf].x, bfr[nf].y);
        }

#pragma unroll
        for (int mf = 0; mf < 4; mf++) {
            int r0g = bm + wm * 64 + mf * 16 + g;
#pragma unroll
            for (int nf = 0; nf < 4; nf++) {
                int col = o * 128 + wn * 32 + nf * 8 + 2 * tq;
                if (r0g < n_nodes)
                    *(__half2*)(g_Ph + (size_t)r0g * 256 + col) =
                        __floats2half2_rn(acc[mf][nf][0], acc[mf][nf][1]);
                if (r0g + 8 < n_nodes)
                    *(__half2*)(g_Ph + (size_t)(r0g + 8) * 256 + col) =
                        __floats2half2_rn(acc[mf][nf][2], acc[mf][nf][3]);
            }
        }
    }
}

// ----------------------------------------------------------------------------
// Kernel 2: edge MLP. 8 warps/block, 16-edge tiles/warp, LDG.128 gather
// (2 edges/iter), A-frags via ldmatrix.x4. W2 B-FRAGMENTS HOISTED INTO
// REGISTERS once per warp (64 regs) — zero B smem traffic in the loop.
// launch_bounds(256,2): 128 regs/thread, 16 warps/SM.
// ----------------------------------------------------------------------------
#define EWARPS 8
#define ETHREADS (EWARPS * 32)
#define HS 136                          // halves per hbuf row (68 words)
#define HBUF_WORDS (16 * (HS / 2))
#define W2F_BYTES 8192
#define EDGE_SMEM_BYTES (W2F_BYTES + 256 + EWARPS * HBUF_WORDS * 4)

__global__ void __launch_bounds__(ETHREADS, 2) edge_mlp_kernel(
    const int*   __restrict__ edge_index,   // [2*E]: src then dst
    const float* __restrict__ eattr,        // [E]
    const float* __restrict__ W1,           // [257*128], row 256 = w1c
    const float* __restrict__ b1,           // [128]
    const float* __restrict__ W2,           // [128*32]
    const float* __restrict__ b2,           // [32]
    const float* __restrict__ W3,           // [32]
    const float* __restrict__ b3,           // [1]
    float*       __restrict__ out,          // [E]
    int n_edges)
{
    extern __shared__ char smem[];
    uint32_t* __restrict__ w2f = (uint32_t*)smem;                  // ldmatrix-packed
    float2* __restrict__ s_bw = (float2*)(smem + W2F_BYTES);       // {b2,w3}[32]
    uint32_t* __restrict__ hb_all = (uint32_t*)(smem + W2F_BYTES + 256);

    const int tid  = threadIdx.x;
    const int wid  = tid >> 5;
    const int lane = tid & 31;
    const int g    = lane >> 2;
    const int tq   = lane & 3;
    const int hl   = lane >> 4;          // half-warp: which of 2 edges per iter
    const int l16  = lane & 15;
    uint32_t* __restrict__ hbuf = hb_all + wid * HBUF_WORDS;

    // --- pack W2 into ldmatrix row order ---
    for (int i = tid; i < 2048; i += ETHREADS) {
        int kc = i >> 8;
        int m  = (i >> 5) & 7;
        int gg = (i >> 2) & 7;
        int ep = i & 3;
        int nt = m >> 1, hb = m & 1;
        int k  = kc * 16 + hb * 8 + 2 * ep;
        int col = nt * 8 + gg;
        __half2 v = __floats2half2_rn(W2[k * 32 + col], W2[(k + 1) * 32 + col]);
        w2f[i] = h2_as_u32(v);
    }
    if (tid < 32) s_bw[tid] = make_float2(b2[tid], W3[tid]);
    __syncthreads();

    // --- hoist ALL B fragments into registers (invariant across tiles) ---
    const uint32_t w2_smem = (uint32_t)__cvta_generic_to_shared(w2f);
    const uint32_t lmB_base = w2_smem + (uint32_t)lane * 16;
    uint32_t Bf[8][8];
#pragma unroll
    for (int kc = 0; kc < 8; kc++) {
        ldmatrix_x4(&Bf[kc][0], lmB_base + (uint32_t)kc * 1024);
        ldmatrix_x4(&Bf[kc][4], lmB_base + (uint32_t)kc * 1024 + 512);
    }

    // --- per-lane layer-1 constants: this lane handles h cols c8..c8+7 ---
    const int c8 = l16 * 8;
    __half2 wc[4], bb[4];
    {
        const float* wrow = W1 + 256 * HID + c8;
#pragma unroll
        for (int j = 0; j < 4; j++) {
            wc[j] = __floats2half2_rn(wrow[2 * j], wrow[2 * j + 1]);
            bb[j] = __floats2half2_rn(b1[c8 + 2 * j], b1[c8 + 2 * j + 1]);
        }
    }
    const __half2 zero2 = __floats2half2_rn(0.f, 0.f);
    const float  b3v = b3[0];

    // ldmatrix base address for A fragments
    const uint32_t hb_smem = (uint32_t)__cvta_generic_to_shared(hbuf);
    const uint32_t lmA_base = hb_smem + (uint32_t)l16 * (HS / 2) * 4 + (uint32_t)hl * 16;

    const int* __restrict__ src = edge_index;
    const int* __restrict__ dst = edge_index + n_edges;

    const int gw = blockIdx.x * EWARPS + wid;
    const int nwarps = gridDim.x * EWARPS;
    const int ntiles = (n_edges + 15) >> 4;

    // ---- prologue: stage first tile's edge data ----
    int sA = 0, dA = 0;
    float eaA = 0.f;
    if (lane < 16 && gw < ntiles) {
        int e = (gw << 4) + lane;
        if (e < n_edges) { sA = src[e]; dA = dst[e]; eaA = eattr[e]; }
    }

    for (int t = gw; t < ntiles; t += nwarps) {
        const int base = t << 4;

        // ---- layer 1: LDG.128 gather, 2 edges per iteration ----
#pragma unroll
        for (int it = 0; it < 8; it++) {
            const int rr = 2 * it + hl;
            int   s  = __shfl_sync(0xffffffffu, sA, rr);
            int   dd = __shfl_sync(0xffffffffu, dA, rr);
            float ea = __shfl_sync(0xffffffffu, eaA, rr);
            __half2 ea2 = __float2half2_rn(ea);
            uint4 ua = *(const uint4*)(g_Ph + (size_t)s  * 256 + c8);
            uint4 ub = *(const uint4*)(g_Ph + (size_t)dd * 256 + 128 + c8);
            uint4 hv;
            {
                __half2 h;
                h = __hadd2(__hadd2(u32_as_h2(ua.x), u32_as_h2(ub.x)), bb[0]);
                hv.x = h2_as_u32(__hmax2(__hfma2(ea2, wc[0], h), zero2));
                h = __hadd2(__hadd2(u32_as_h2(ua.y), u32_as_h2(ub.y)), bb[1]);
                hv.y = h2_as_u32(__hmax2(__hfma2(ea2, wc[1], h), zero2));
                h = __hadd2(__hadd2(u32_as_h2(ua.z), u32_as_h2(ub.z)), bb[2]);
                hv.z = h2_as_u32(__hmax2(__hfma2(ea2, wc[2], h), zero2));
                h = __hadd2(__hadd2(u32_as_h2(ua.w), u32_as_h2(ub.w)), bb[3]);
                hv.w = h2_as_u32(__hmax2(__hfma2(ea2, wc[3], h), zero2));
            }
            *(uint4*)(hbuf + rr * (HS / 2) + (c8 >> 1)) = hv;
        }
        __syncwarp();

        // ---- prefetch next tile's edge indices (hidden under MMA) ----
        int sN = 0, dN = 0;
        float eaN = 0.f;
        {
            int t2 = t + nwarps;
            if (lane < 16 && t2 < ntiles) {
                int e = (t2 << 4) + lane;
                if (e < n_edges) { sN = src[e]; dN = dst[e]; eaN = eattr[e]; }
            }
        }

        // ---- layer 2: fp16 mma; A via ldmatrix, B from registers ----
        float dacc[4][4];
#pragma unroll
        for (int nt = 0; nt < 4; nt++)
#pragma unroll
            for (int j = 0; j < 4; j++) dacc[nt][j] = 0.f;

#pragma unroll
        for (int kc = 0; kc < 8; kc++) {
            uint32_t a[4];
            ldmatrix_x4(a, lmA_base + (uint32_t)kc * 32);
            mma_f16(dacc[0], a, Bf[kc][0], Bf[kc][1]);
            mma_f16(dacc[1], a, Bf[kc][2], Bf[kc][3]);
            mma_f16(dacc[2], a, Bf[kc][4], Bf[kc][5]);
            mma_f16(dacc[3], a, Bf[kc][6], Bf[kc][7]);
        }
        __syncwarp();   // hbuf safe before next tile overwrites

        // ---- layer 3: +b2, relu, *W3, quad-reduce, sigmoid ----
        float acc0 = 0.f, acc1 = 0.f;   // rows base+g and base+g+8
#pragma unroll
        for (int nt = 0; nt < 4; nt++) {
#pragma unroll
            for (int i = 0; i < 2; i++) {
                int col = nt * 8 + 2 * tq + i;
                float2 bw = s_bw[col];
                acc0 = fmaf(fmaxf(dacc[nt][i]     + bw.x, 0.f), bw.y, acc0);
                acc1 = fmaf(fmaxf(dacc[nt][2 + i] + bw.x, 0.f), bw.y, acc1);
            }
        }
        acc0 += __shfl_xor_sync(0xffffffffu, acc0, 1);
        acc0 += __shfl_xor_sync(0xffffffffu, acc0, 2);
        acc1 += __shfl_xor_sync(0xffffffffu, acc1, 1);
        acc1 += __shfl_xor_sync(0xffffffffu, acc1, 2);
        if (tq == 0) {
            int e0 = base + g;
            int e1 = base + g + 8;
            if (e0 < n_edges) {
                float z = acc0 + b3v;
                out[e0] = 1.f / (1.f + __expf(-z));
            }
            if (e1 < n_edges) {
                float z = acc1 + b3v;
                out[e1] = 1.f / (1.f + __expf(-z));
            }
        }

        sA = sN; dA = dN; eaA = eaN;
    }
}

// ----------------------------------------------------------------------------
// Launch
// ----------------------------------------------------------------------------
extern "C" void kernel_launch(void* const* d_in, const int* in_sizes, int n_in,
                              void* d_out, int out_size)
{
    const float* x  = (const float*)d_in[0];
    const int*   ei = (const int*)d_in[1];
    const float* ea = (const float*)d_in[2];
    const float* W1 = (const float*)d_in[3];
    const float* b1 = (const float*)d_in[4];
    const float* W2 = (const float*)d_in[5];
    const float* b2 = (const float*)d_in[6];
    const float* W3 = (const float*)d_in[7];
    const float* b3 = (const float*)d_in[8];
    float*       out = (float*)d_out;

    const int n_nodes = in_sizes[0] / HID;     // 100000
    const int n_edges = in_sizes[2];           // 1000000

    static int smem_set = 0;
    if (!smem_set) {
        cudaFuncSetAttribute(node_proj_mma_kernel,
                             cudaFuncAttributeMaxDynamicSharedMemorySize, NP_SMEM_BYTES);
        cudaFuncSetAttribute(edge_mlp_kernel,
                             cudaFuncAttributeMaxDynamicSharedMemorySize, EDGE_SMEM_BYTES);
        smem_set = 1;
    }

    // Kernel 0: pack W1 fragments (L2-hot afterwards)
    pack_w1_kernel<<<32, 256>>>(W1);

    // Kernel 1: node projections (both halves per block, x read once)
    const int g1 = (n_nodes + 127) / 128;
    node_proj_mma_kernel<<<g1, 256, NP_SMEM_BYTES>>>(x, n_nodes);

    // Kernel 2: edge MLP (B frags register-resident; 2 blocks/SM, 16 warps)
    const int blocks = 296;
    edge_mlp_kernel<<<blocks, ETHREADS, EDGE_SMEM_BYTES>>>(
        ei, ea, W1, b1, W2, b2, W3, b3, out, n_edges);
}